// round 1
// baseline (speedup 1.0000x reference)
#include <cuda_runtime.h>
#include <cstdint>

// VolumeRenderer: per-ray exclusive-cumprod transmittance * alpha, dot with rgb.
// alpha: [R, 128, 1] f32, rgbs: [R, 128, 3] f32 -> out [R, 3] f32.
// One warp per ray; lane l handles samples [4l, 4l+4).

#define EPS 1e-10f

__global__ __launch_bounds__(256) void volume_render_kernel(
    const float* __restrict__ alpha,
    const float* __restrict__ rgbs,
    float* __restrict__ out,
    int R)
{
    const int warp_id = (blockIdx.x * blockDim.x + threadIdx.x) >> 5;
    const int lane = threadIdx.x & 31;
    if (warp_id >= R) return;

    const size_t ray = (size_t)warp_id;

    // ---- load 4 alphas (contiguous per warp: 128 floats) ----
    const float4 a4 = *reinterpret_cast<const float4*>(alpha + ray * 128 + lane * 4);

    const float t0 = 1.0f - a4.x + EPS;
    const float t1 = 1.0f - a4.y + EPS;
    const float t2 = 1.0f - a4.z + EPS;
    const float t3 = 1.0f - a4.w + EPS;

    // per-lane product of the 4 transmittance factors
    const float local = ((t0 * t1) * (t2 * t3));

    // inclusive warp scan (product) over lanes
    float incl = local;
    #pragma unroll
    for (int off = 1; off < 32; off <<= 1) {
        float v = __shfl_up_sync(0xffffffffu, incl, off);
        if (lane >= off) incl *= v;
    }
    // exclusive prefix for this lane
    float excl = __shfl_up_sync(0xffffffffu, incl, 1);
    if (lane == 0) excl = 1.0f;

    // ---- load 12 rgb floats (3 x float4, 16B-aligned: base 1536B*ray + 48B*lane) ----
    const float4* rg = reinterpret_cast<const float4*>(rgbs + ray * 384 + lane * 12);
    const float4 r0 = rg[0];
    const float4 r1 = rg[1];
    const float4 r2 = rg[2];

    // ---- weighted accumulation over this lane's 4 samples ----
    float acc0 = 0.0f, acc1 = 0.0f, acc2 = 0.0f;
    float tr = excl;

    float w = tr * a4.x;
    acc0 = fmaf(w, r0.x, acc0); acc1 = fmaf(w, r0.y, acc1); acc2 = fmaf(w, r0.z, acc2);
    tr *= t0;

    w = tr * a4.y;
    acc0 = fmaf(w, r0.w, acc0); acc1 = fmaf(w, r1.x, acc1); acc2 = fmaf(w, r1.y, acc2);
    tr *= t1;

    w = tr * a4.z;
    acc0 = fmaf(w, r1.z, acc0); acc1 = fmaf(w, r1.w, acc1); acc2 = fmaf(w, r2.x, acc2);
    tr *= t2;

    w = tr * a4.w;
    acc0 = fmaf(w, r2.y, acc0); acc1 = fmaf(w, r2.z, acc1); acc2 = fmaf(w, r2.w, acc2);

    // ---- butterfly reduce the 3 channels across the warp ----
    #pragma unroll
    for (int off = 16; off > 0; off >>= 1) {
        acc0 += __shfl_xor_sync(0xffffffffu, acc0, off);
        acc1 += __shfl_xor_sync(0xffffffffu, acc1, off);
        acc2 += __shfl_xor_sync(0xffffffffu, acc2, off);
    }

    // lanes 0..2 write one channel each -> contiguous 12B store
    if (lane < 3) {
        float v = (lane == 0) ? acc0 : ((lane == 1) ? acc1 : acc2);
        out[ray * 3 + lane] = v;
    }
}

extern "C" void kernel_launch(void* const* d_in, const int* in_sizes, int n_in,
                              void* d_out, int out_size)
{
    const float* alpha = (const float*)d_in[0];   // [R,128,1]
    const float* rgbs  = (const float*)d_in[1];   // [R,128,3]
    float* out = (float*)d_out;                   // [R,3]

    const int R = in_sizes[0] / 128;

    const int threads = 256;              // 8 warps/block = 8 rays/block
    const int rays_per_block = threads / 32;
    const int blocks = (R + rays_per_block - 1) / rays_per_block;

    volume_render_kernel<<<blocks, threads>>>(alpha, rgbs, out, R);
}

// round 2
// speedup vs baseline: 1.0059x; 1.0059x over previous
#include <cuda_runtime.h>
#include <cstdint>

// VolumeRenderer: per-ray exclusive-cumprod transmittance * alpha, dot with rgb.
// alpha: [R, 128, 1] f32, rgbs: [R, 128, 3] f32 -> out [R, 3] f32.
// One warp handles TWO rays; lane l handles samples [4l, 4l+4) of each.
// All 8 LDG.128 front-batched for max MLP; the two scan chains interleave.

#define EPS 1e-10f

__device__ __forceinline__ float4 ldcs4(const float4* p) {
    return __ldcs(p);
}

__global__ __launch_bounds__(256) void volume_render_kernel2(
    const float* __restrict__ alpha,
    const float* __restrict__ rgbs,
    float* __restrict__ out,
    int R)
{
    const int warp_id = (blockIdx.x * blockDim.x + threadIdx.x) >> 5;
    const int lane = threadIdx.x & 31;

    const size_t rayA = (size_t)warp_id * 2;
    const size_t rayB = rayA + 1;
    if (rayA >= (size_t)R) return;
    const bool hasB = (rayB < (size_t)R);

    // ---- front-batch all loads (8 x LDG.128) ----
    const float4 aA = ldcs4(reinterpret_cast<const float4*>(alpha + rayA * 128) + lane);
    const float4* rgA = reinterpret_cast<const float4*>(rgbs + rayA * 384) + lane * 3;
    const float4 rA0 = ldcs4(rgA + 0);
    const float4 rA1 = ldcs4(rgA + 1);
    const float4 rA2 = ldcs4(rgA + 2);

    float4 aB = make_float4(0.f, 0.f, 0.f, 0.f);
    float4 rB0 = aB, rB1 = aB, rB2 = aB;
    if (hasB) {
        aB = ldcs4(reinterpret_cast<const float4*>(alpha + rayB * 128) + lane);
        const float4* rgB = reinterpret_cast<const float4*>(rgbs + rayB * 384) + lane * 3;
        rB0 = ldcs4(rgB + 0);
        rB1 = ldcs4(rgB + 1);
        rB2 = ldcs4(rgB + 2);
    }

    // ---- transmittance factors ----
    const float tA0 = 1.0f - aA.x + EPS, tA1 = 1.0f - aA.y + EPS;
    const float tA2 = 1.0f - aA.z + EPS, tA3 = 1.0f - aA.w + EPS;
    const float tB0 = 1.0f - aB.x + EPS, tB1 = 1.0f - aB.y + EPS;
    const float tB2 = 1.0f - aB.z + EPS, tB3 = 1.0f - aB.w + EPS;

    float inclA = (tA0 * tA1) * (tA2 * tA3);
    float inclB = (tB0 * tB1) * (tB2 * tB3);

    // ---- two interleaved inclusive warp scans (product) ----
    #pragma unroll
    for (int off = 1; off < 32; off <<= 1) {
        const float vA = __shfl_up_sync(0xffffffffu, inclA, off);
        const float vB = __shfl_up_sync(0xffffffffu, inclB, off);
        if (lane >= off) { inclA *= vA; inclB *= vB; }
    }
    float exclA = __shfl_up_sync(0xffffffffu, inclA, 1);
    float exclB = __shfl_up_sync(0xffffffffu, inclB, 1);
    if (lane == 0) { exclA = 1.0f; exclB = 1.0f; }

    // ---- weighted accumulation, ray A ----
    float aacc0 = 0.f, aacc1 = 0.f, aacc2 = 0.f;
    {
        float tr = exclA, w;
        w = tr * aA.x; aacc0 = fmaf(w, rA0.x, aacc0); aacc1 = fmaf(w, rA0.y, aacc1); aacc2 = fmaf(w, rA0.z, aacc2); tr *= tA0;
        w = tr * aA.y; aacc0 = fmaf(w, rA0.w, aacc0); aacc1 = fmaf(w, rA1.x, aacc1); aacc2 = fmaf(w, rA1.y, aacc2); tr *= tA1;
        w = tr * aA.z; aacc0 = fmaf(w, rA1.z, aacc0); aacc1 = fmaf(w, rA1.w, aacc1); aacc2 = fmaf(w, rA2.x, aacc2); tr *= tA2;
        w = tr * aA.w; aacc0 = fmaf(w, rA2.y, aacc0); aacc1 = fmaf(w, rA2.z, aacc1); aacc2 = fmaf(w, rA2.w, aacc2);
    }
    // ---- weighted accumulation, ray B ----
    float bacc0 = 0.f, bacc1 = 0.f, bacc2 = 0.f;
    {
        float tr = exclB, w;
        w = tr * aB.x; bacc0 = fmaf(w, rB0.x, bacc0); bacc1 = fmaf(w, rB0.y, bacc1); bacc2 = fmaf(w, rB0.z, bacc2); tr *= tB0;
        w = tr * aB.y; bacc0 = fmaf(w, rB0.w, bacc0); bacc1 = fmaf(w, rB1.x, bacc1); bacc2 = fmaf(w, rB1.y, bacc2); tr *= tB1;
        w = tr * aB.z; bacc0 = fmaf(w, rB1.z, bacc0); bacc1 = fmaf(w, rB1.w, bacc1); bacc2 = fmaf(w, rB2.x, bacc2); tr *= tB2;
        w = tr * aB.w; bacc0 = fmaf(w, rB2.y, bacc0); bacc1 = fmaf(w, rB2.z, bacc1); bacc2 = fmaf(w, rB2.w, bacc2);
    }

    // ---- interleaved butterfly reductions (6 independent chains) ----
    #pragma unroll
    for (int off = 16; off > 0; off >>= 1) {
        aacc0 += __shfl_xor_sync(0xffffffffu, aacc0, off);
        aacc1 += __shfl_xor_sync(0xffffffffu, aacc1, off);
        aacc2 += __shfl_xor_sync(0xffffffffu, aacc2, off);
        bacc0 += __shfl_xor_sync(0xffffffffu, bacc0, off);
        bacc1 += __shfl_xor_sync(0xffffffffu, bacc1, off);
        bacc2 += __shfl_xor_sync(0xffffffffu, bacc2, off);
    }

    // lanes 0..2 write ray A channels, lanes 3..5 write ray B channels
    // (contiguous 24B store across the warp when both rays valid)
    if (lane < 3) {
        const float v = (lane == 0) ? aacc0 : ((lane == 1) ? aacc1 : aacc2);
        out[rayA * 3 + lane] = v;
    } else if (hasB && lane < 6) {
        const int c = lane - 3;
        const float v = (c == 0) ? bacc0 : ((c == 1) ? bacc1 : bacc2);
        out[rayB * 3 + c] = v;
    }
}

extern "C" void kernel_launch(void* const* d_in, const int* in_sizes, int n_in,
                              void* d_out, int out_size)
{
    const float* alpha = (const float*)d_in[0];   // [R,128,1]
    const float* rgbs  = (const float*)d_in[1];   // [R,128,3]
    float* out = (float*)d_out;                   // [R,3]

    const int R = in_sizes[0] / 128;

    const int threads = 256;                        // 8 warps/block = 16 rays/block
    const int rays_per_block = (threads / 32) * 2;
    const int blocks = (R + rays_per_block - 1) / rays_per_block;

    volume_render_kernel2<<<blocks, threads>>>(alpha, rgbs, out, R);
}